// round 16
// baseline (speedup 1.0000x reference)
#include <cuda_runtime.h>
#include <cuda_bf16.h>
#include <cstdint>

#define NTOK 65536
#define CD   128
#define SEQ  512
#define NGR  128

__device__ float g_bufA[(size_t)NTOK * CD];
__device__ float g_bufB[(size_t)NTOK * CD];
__device__ float g_state[NGR * 16 * CD];  // per-(graph, 32-segment, channel) weighted sums

// bf16 hi/lo weight images (row-major [n][k])
__device__ __nv_bfloat16 g_WinH[3][256 * 128];
__device__ __nv_bfloat16 g_WinL[3][256 * 128];
__device__ __nv_bfloat16 g_WoutH[3][128 * 128];
__device__ __nv_bfloat16 g_WoutL[3][128 * 128];
__device__ __nv_bfloat16 g_WpH[128 * 64];
__device__ __nv_bfloat16 g_WpL[128 * 64];

__device__ __forceinline__ unsigned int smem_u32(const void* p) {
    unsigned int a;
    asm("{ .reg .u64 t; cvta.to.shared.u64 t, %1; cvt.u32.u64 %0, t; }" : "=r"(a) : "l"(p));
    return a;
}

#define LDSM4(v, addr) \
    asm volatile("ldmatrix.sync.aligned.m8n8.x4.shared.b16 {%0,%1,%2,%3}, [%4];" \
                 : "=r"((v).x), "=r"((v).y), "=r"((v).z), "=r"((v).w) : "r"(addr))

#define MMA_BF16(d, a, b0, b1) \
    asm volatile("mma.sync.aligned.m16n8k16.row.col.f32.bf16.bf16.f32 " \
                 "{%0,%1,%2,%3}, {%4,%5,%6,%7}, {%8,%9}, {%0,%1,%2,%3};" \
                 : "+f"((d)[0]), "+f"((d)[1]), "+f"((d)[2]), "+f"((d)[3]) \
                 : "r"((a).x), "r"((a).y), "r"((a).z), "r"((a).w), "r"(b0), "r"(b1))

// 12 MMAs: 3-term bf16 split for one (m32 x n16) block
#define MMA_BLOCK(c0, c1, c2, c3, ah0, ah1, al0, al1, bh, bl) \
    do { \
        MMA_BF16(c0, ah0, bh.x, bh.y); \
        MMA_BF16(c0, ah0, bl.x, bl.y); \
        MMA_BF16(c0, al0, bh.x, bh.y); \
        MMA_BF16(c1, ah0, bh.z, bh.w); \
        MMA_BF16(c1, ah0, bl.z, bl.w); \
        MMA_BF16(c1, al0, bh.z, bh.w); \
        MMA_BF16(c2, ah1, bh.x, bh.y); \
        MMA_BF16(c2, ah1, bl.x, bl.y); \
        MMA_BF16(c2, al1, bh.x, bh.y); \
        MMA_BF16(c3, ah1, bh.z, bh.w); \
        MMA_BF16(c3, ah1, bl.z, bl.w); \
        MMA_BF16(c3, al1, bh.z, bh.w); \
    } while (0)

// fused conv_state: block covers rows row0..row0+63 (2 segments of 32).
// Q[g][seg][c] = sum_{j=0..31} rho^j * out[32*seg + j][c], read back via L1 after syncthreads.
__device__ __forceinline__ void fused_state(const float* __restrict__ ltau, int tid,
                                            size_t row0) {
    const int c  = tid & 127;
    const int ts = tid >> 7;              // 0..1
    const int b   = (int)(row0 >> 9);
    const int seg = (int)((row0 & 511) >> 5) + ts;
    float tau = fmaxf(expf(__ldg(&ltau[c])), 0.001f);
    float rho = expf(-1.0f / tau);
    const float* xp = g_bufA + (row0 + (size_t)ts * 32) * CD + c;
    float P = 0.f;
#pragma unroll 8
    for (int j = 31; j >= 0; --j)         // descending: out[+j] gets weight rho^j
        P = fmaf(rho, P, xp[j * CD]);
    g_state[(b * 16 + seg) * CD + c] = P;
}

// ---------------- weight staging: fp32 -> bf16 hi/lo (96 blocks) ----------------
__global__ __launch_bounds__(256) void stage_w_kernel(const float* __restrict__ W_in,
                                                      const float* __restrict__ W_out,
                                                      const float* __restrict__ Wp) {
    const int d = blockIdx.x >> 5;        // 0..2
    const int gt = (blockIdx.x & 31) * 256 + threadIdx.x;   // 0..8191 within depth
    for (int i = gt; i < 256 * 128; i += 8192) {
        float v = W_in[d * 256 * 128 + i];
        __nv_bfloat16 h = __float2bfloat16(v);
        g_WinH[d][i] = h;
        g_WinL[d][i] = __float2bfloat16(v - __bfloat162float(h));
    }
    for (int i = gt; i < 128 * 128; i += 8192) {
        float v = W_out[d * 128 * 128 + i];
        __nv_bfloat16 h = __float2bfloat16(v);
        g_WoutH[d][i] = h;
        g_WoutL[d][i] = __float2bfloat16(v - __bfloat162float(h));
    }
    if (d == 0) {
        for (int i = gt; i < 128 * 64; i += 8192) {
            float v = Wp[i];
            __nv_bfloat16 h = __float2bfloat16(v);
            g_WpH[i] = h;
            g_WpL[i] = __float2bfloat16(v - __bfloat162float(h));
        }
    }
}

// ---------------- proj via mma.sync + fused depth-0 conv state ----------------
#define PJ_XH 0
#define PJ_XL 9216
#define PJ_WH 18432
#define PJ_WL 36864
#define PJ_SMEM 55296

__global__ __launch_bounds__(256) void proj_mma_kernel(const float* __restrict__ x,
                                                       const float* __restrict__ bproj,
                                                       const float* __restrict__ ltau0) {
    extern __shared__ char smem[];
    const unsigned sb = smem_u32(smem);
    const int tid = threadIdx.x;
    const int wid = tid >> 5, lane = tid & 31;
    const int r0 = (wid >> 2) * 32;
    const int n0 = (wid & 3) * 32;
    const size_t row0 = (size_t)blockIdx.x * 64;

#pragma unroll
    for (int t = 0; t < 8; ++t) {
        int idx = tid + t * 256;          // pair index over 64 x 32
        int r = idx >> 5, kp = idx & 31;
        float2 v2 = *(const float2*)&x[(row0 + r) * 64 + 2 * kp];
        __nv_bfloat16 h0 = __float2bfloat16(v2.x), h1 = __float2bfloat16(v2.y);
        __nv_bfloat16 l0 = __float2bfloat16(v2.x - __bfloat162float(h0));
        __nv_bfloat16 l1 = __float2bfloat16(v2.y - __bfloat162float(h1));
        __nv_bfloat162 hp = __halves2bfloat162(h0, h1);
        __nv_bfloat162 lp = __halves2bfloat162(l0, l1);
        *(unsigned*)(smem + PJ_XH + r * 144 + kp * 4) = *(unsigned*)&hp;
        *(unsigned*)(smem + PJ_XL + r * 144 + kp * 4) = *(unsigned*)&lp;
    }
#pragma unroll
    for (int t = 0; t < 4; ++t) {
        int i = tid + t * 256;            // chunk over 128 x 8
        int r = i >> 3, ck = i & 7;
        *(uint4*)(smem + PJ_WH + r * 144 + ck * 16) = *(const uint4*)((const char*)(g_WpH + r * 64) + ck * 16);
        *(uint4*)(smem + PJ_WL + r * 144 + ck * 16) = *(const uint4*)((const char*)(g_WpL + r * 64) + ck * 16);
    }
    __syncthreads();

    const unsigned browb = (unsigned)((lane & 7) + ((lane & 16) >> 1));
    const unsigned bcolb = (unsigned)(lane & 8);
    float acc[2][4][4];
#pragma unroll
    for (int m = 0; m < 2; ++m)
#pragma unroll
        for (int n = 0; n < 4; ++n)
#pragma unroll
            for (int j = 0; j < 4; ++j) acc[m][n][j] = 0.f;

#pragma unroll
    for (int ks = 0; ks < 4; ++ks) {
        const int k0 = ks * 16;
        unsigned aoff = (unsigned)(r0 + (lane & 15)) * 144u
                      + (unsigned)(k0 + ((lane & 16) >> 1)) * 2u;
        uint4 ah0, ah1, al0, al1;
        LDSM4(ah0, sb + PJ_XH + aoff);
        LDSM4(ah1, sb + PJ_XH + aoff + 16 * 144);
        LDSM4(al0, sb + PJ_XL + aoff);
        LDSM4(al1, sb + PJ_XL + aoff + 16 * 144);
#pragma unroll
        for (int nb = 0; nb < 2; ++nb) {
            unsigned boff = (unsigned)(n0 + nb * 16 + browb) * 144u
                          + (bcolb + (unsigned)k0) * 2u;
            uint4 bh, bl;
            LDSM4(bh, sb + PJ_WH + boff);
            LDSM4(bl, sb + PJ_WL + boff);
            MMA_BLOCK(acc[0][nb * 2], acc[0][nb * 2 + 1], acc[1][nb * 2], acc[1][nb * 2 + 1],
                      ah0, ah1, al0, al1, bh, bl);
        }
    }
    const int rA = (lane >> 2);
    const int cB = (lane & 3) * 2;
#pragma unroll
    for (int m = 0; m < 2; ++m) {
#pragma unroll
        for (int n = 0; n < 4; ++n) {
            const int col = n0 + n * 8 + cB;
            const float bb0 = __ldg(&bproj[col]), bb1 = __ldg(&bproj[col + 1]);
#pragma unroll
            for (int rr = 0; rr < 2; ++rr) {
                const int r = r0 + m * 16 + rA + rr * 8;
                float2 v = make_float2(acc[m][n][rr * 2] + bb0, acc[m][n][rr * 2 + 1] + bb1);
                *(float2*)&g_bufA[(row0 + r) * CD + col] = v;
            }
        }
    }
    __syncthreads();                       // make this block's g_bufA writes visible
    fused_state(ltau0, tid, row0);
}

// ---------------- conv phase B: emit using 8 combined states (R13/R15) ----------------
__global__ __launch_bounds__(128) void conv_emit_kernel(const float* __restrict__ log_tau_d) {
    const int b = blockIdx.x >> 4;
    const int q = blockIdx.x & 15;
    const int c = threadIdx.x;

    float tau   = fmaxf(expf(log_tau_d[c]), 0.001f);
    float it    = 1.0f / tau;
    float rho   = expf(-it);
    float rho32 = expf(-32.0f * it);
    float rhoK  = expf(-256.0f * it);
    float den   = 1.0f - rho;
    float S     = (den > 1e-20f) ? (1.0f - rhoK) / den : 256.0f;
    float scale = 1.0f / (S + 1e-8f);

    const float* xp = g_bufA + (size_t)b * SEQ * CD + c;
    float*       yp = g_bufB + (size_t)b * SEQ * CD + c;

    float acc = 0.f;
#pragma unroll
    for (int dd = 0; dd < 8; ++dd) {   // Q_q gets rho32^7, Q_{q-7} gets rho32^0
        int tseg = q - dd;
        float P = (tseg >= 0) ? g_state[(b * 16 + tseg) * CD + c] : 0.f;
        acc = fmaf(rho32, acc, P);
    }

    int l = q * 32 + 31;
#pragma unroll 8
    for (int n = 0; n < 32; ++n, --l) {
        yp[l * CD] = acc * scale;
        float xold = (l >= 256) ? xp[(l - 256) * CD] : 0.f;
        float xtop = xp[l * CD];
        acc = fmaf(rho, acc, fmaf(-rhoK, xtop, xold));
    }
}

// ---------------- mma.sync fused MLP + fused next-depth conv state ----------------
#define SM_YH   0
#define SM_YL   17408
#define SM_W    34816
#define SM_WLO  71680
#define SM_UH   SM_YH
#define SM_UL   SM_YL
#define SM_ZB   SM_YH
#define MMA_SMEM_BYTES 108544

__device__ __forceinline__ void copy_w_pair(char* smem, int tid,
                                            const __nv_bfloat16* __restrict__ h0,
                                            const __nv_bfloat16* __restrict__ l0, int co0,
                                            const __nv_bfloat16* __restrict__ h1,
                                            const __nv_bfloat16* __restrict__ l1, int co1) {
#pragma unroll
    for (int t = 0; t < 8; ++t) {
        int i = tid + t * 256;            // chunk index over 256 rows x 8 chunks
        int r = i >> 3, ck = i & 7;
        const __nv_bfloat16* sH = (r < 128) ? (h0 + r * 128 + co0) : (h1 + (r - 128) * 128 + co1);
        const __nv_bfloat16* sL = (r < 128) ? (l0 + r * 128 + co0) : (l1 + (r - 128) * 128 + co1);
        *(uint4*)(smem + SM_W + r * 144 + ck * 16)   = *(const uint4*)((const char*)sH + ck * 16);
        *(uint4*)(smem + SM_WLO + r * 144 + ck * 16) = *(const uint4*)((const char*)sL + ck * 16);
    }
}

__device__ __forceinline__ void gemm_pair(unsigned sb, unsigned aH, unsigned aL,
                                          int khalf, int r0, int n0, int lane,
                                          float accA[2][4][4], float accG[2][4][4]) {
    const unsigned browb = (unsigned)((lane & 7) + ((lane & 16) >> 1));
    const unsigned bcolb = (unsigned)(lane & 8);
#pragma unroll
    for (int ks = 0; ks < 4; ++ks) {
        const int kA = khalf * 64 + ks * 16;
        unsigned aoff = (unsigned)(r0 + (lane & 15)) * 272u
                      + (unsigned)(kA + ((lane & 16) >> 1)) * 2u;
        uint4 ah0, ah1, al0, al1;
        LDSM4(ah0, sb + aH + aoff);
        LDSM4(ah1, sb + aH + aoff + 16 * 272);
        LDSM4(al0, sb + aL + aoff);
        LDSM4(al1, sb + aL + aoff + 16 * 272);
#pragma unroll
        for (int tgt = 0; tgt < 2; ++tgt) {
            float (*acc)[4][4] = tgt ? (float (*)[4][4])accG : (float (*)[4][4])accA;
#pragma unroll
            for (int nb = 0; nb < 2; ++nb) {
                unsigned boff = (unsigned)(tgt * 128 + n0 + nb * 16 + browb) * 144u
                              + (bcolb + (unsigned)(ks * 16)) * 2u;
                uint4 bh, bl;
                LDSM4(bh, sb + SM_W + boff);
                LDSM4(bl, sb + SM_WLO + boff);
                MMA_BLOCK(acc[0][nb * 2], acc[0][nb * 2 + 1], acc[1][nb * 2], acc[1][nb * 2 + 1],
                          ah0, ah1, al0, al1, bh, bl);
            }
        }
    }
}

__global__ __launch_bounds__(256, 2) void mlp_mma_kernel(int depth,
                                                         const float* __restrict__ b_in,
                                                         const float* __restrict__ b_out,
                                                         const float* __restrict__ gamma,
                                                         const float* __restrict__ beta,
                                                         const float* __restrict__ ltau_next) {
    extern __shared__ char smem[];
    const unsigned sb = smem_u32(smem);
    const int tid = threadIdx.x;
    const int wid = tid >> 5, lane = tid & 31;
    const int r0 = (wid >> 2) * 32;
    const int n0 = (wid & 3) * 32;
    const size_t row0 = (size_t)blockIdx.x * 64;

    const __nv_bfloat16* WiH = g_WinH[depth];
    const __nv_bfloat16* WiL = g_WinL[depth];
    const __nv_bfloat16* WoH = g_WoutH[depth];
    const __nv_bfloat16* WoL = g_WoutL[depth];

    copy_w_pair(smem, tid, WiH, WiL, 0, WiH + 128 * 128, WiL + 128 * 128, 0);
#pragma unroll
    for (int t = 0; t < 16; ++t) {
        int idx = tid + t * 256;
        int r = idx >> 6, kp = idx & 63;
        float2 y2 = *(const float2*)&g_bufB[(row0 + r) * CD + 2 * kp];
        __nv_bfloat16 h0 = __float2bfloat16(y2.x), h1 = __float2bfloat16(y2.y);
        __nv_bfloat16 l0 = __float2bfloat16(y2.x - __bfloat162float(h0));
        __nv_bfloat16 l1 = __float2bfloat16(y2.y - __bfloat162float(h1));
        __nv_bfloat162 hp = __halves2bfloat162(h0, h1);
        __nv_bfloat162 lp = __halves2bfloat162(l0, l1);
        *(unsigned*)(smem + SM_YH + r * 272 + kp * 4) = *(unsigned*)&hp;
        *(unsigned*)(smem + SM_YL + r * 272 + kp * 4) = *(unsigned*)&lp;
    }
    __syncthreads();

    float acc_a[2][4][4], acc_g[2][4][4];
#pragma unroll
    for (int m = 0; m < 2; ++m)
#pragma unroll
        for (int n = 0; n < 4; ++n)
#pragma unroll
            for (int j = 0; j < 4; ++j) { acc_a[m][n][j] = 0.f; acc_g[m][n][j] = 0.f; }

    gemm_pair(sb, SM_YH, SM_YL, 0, r0, n0, lane, acc_a, acc_g);
    __syncthreads();
    copy_w_pair(smem, tid, WiH, WiL, 64, WiH + 128 * 128, WiL + 128 * 128, 64);
    __syncthreads();
    gemm_pair(sb, SM_YH, SM_YL, 1, r0, n0, lane, acc_a, acc_g);
    __syncthreads();

    const int rA = (lane >> 2);
    const int cB = (lane & 3) * 2;

#pragma unroll
    for (int m = 0; m < 2; ++m) {
#pragma unroll
        for (int n = 0; n < 4; ++n) {
            const int col = n0 + n * 8 + cB;
            const float ba0 = __ldg(&b_in[col]),       ba1 = __ldg(&b_in[col + 1]);
            const float bg0 = __ldg(&b_in[128 + col]), bg1 = __ldg(&b_in[128 + col + 1]);
#pragma unroll
            for (int rr = 0; rr < 2; ++rr) {
                const int r = r0 + m * 16 + rA + rr * 8;
                float av0 = acc_a[m][n][rr * 2]     + ba0;
                float av1 = acc_a[m][n][rr * 2 + 1] + ba1;
                float gv0 = acc_g[m][n][rr * 2]     + bg0;
                float gv1 = acc_g[m][n][rr * 2 + 1] + bg1;
                float u0 = av0 / (1.0f + expf(-gv0));
                float u1 = av1 / (1.0f + expf(-gv1));
                __nv_bfloat16 h0 = __float2bfloat16(u0), h1 = __float2bfloat16(u1);
                __nv_bfloat16 l0 = __float2bfloat16(u0 - __bfloat162float(h0));
                __nv_bfloat16 l1 = __float2bfloat16(u1 - __bfloat162float(h1));
                __nv_bfloat162 hp = __halves2bfloat162(h0, h1);
                __nv_bfloat162 lp = __halves2bfloat162(l0, l1);
                *(unsigned*)(smem + SM_UH + r * 272 + col * 2) = *(unsigned*)&hp;
                *(unsigned*)(smem + SM_UL + r * 272 + col * 2) = *(unsigned*)&lp;
            }
        }
    }
    copy_w_pair(smem, tid, WoH, WoL, 0, WoH, WoL, 64);
    __syncthreads();

    float acc2[2][4][4];
#pragma unroll
    for (int m = 0; m < 2; ++m)
#pragma unroll
        for (int n = 0; n < 4; ++n)
#pragma unroll
            for (int j = 0; j < 4; ++j) acc2[m][n][j] = 0.f;
    {
        const unsigned browb = (unsigned)((lane & 7) + ((lane & 16) >> 1));
        const unsigned bcolb = (unsigned)(lane & 8);
#pragma unroll
        for (int khalf = 0; khalf < 2; ++khalf) {
#pragma unroll
            for (int ks = 0; ks < 4; ++ks) {
                const int kA = khalf * 64 + ks * 16;
                unsigned aoff = (unsigned)(r0 + (lane & 15)) * 272u
                              + (unsigned)(kA + ((lane & 16) >> 1)) * 2u;
                uint4 ah0, ah1, al0, al1;
                LDSM4(ah0, sb + SM_UH + aoff);
                LDSM4(ah1, sb + SM_UH + aoff + 16 * 272);
                LDSM4(al0, sb + SM_UL + aoff);
                LDSM4(al1, sb + SM_UL + aoff + 16 * 272);
#pragma unroll
                for (int nb = 0; nb < 2; ++nb) {
                    unsigned boff = (unsigned)(khalf * 128 + n0 + nb * 16 + browb) * 144u
                                  + (bcolb + (unsigned)(ks * 16)) * 2u;
                    uint4 bh, bl;
                    LDSM4(bh, sb + SM_W + boff);
                    LDSM4(bl, sb + SM_WLO + boff);
                    MMA_BLOCK(acc2[0][nb * 2], acc2[0][nb * 2 + 1], acc2[1][nb * 2], acc2[1][nb * 2 + 1],
                              ah0, ah1, al0, al1, bh, bl);
                }
            }
        }
    }
    __syncthreads();

    float* zbuf = (float*)(smem + SM_ZB);
#pragma unroll
    for (int m = 0; m < 2; ++m) {
#pragma unroll
        for (int n = 0; n < 4; ++n) {
            const int col = n0 + n * 8 + cB;
            const float bb0 = __ldg(&b_out[col]), bb1 = __ldg(&b_out[col + 1]);
#pragma unroll
            for (int rr = 0; rr < 2; ++rr) {
                const int r = r0 + m * 16 + rA + rr * 8;
                float2 y2 = *(const float2*)&g_bufB[(row0 + r) * CD + col];
                zbuf[r * 132 + col]     = acc2[m][n][rr * 2]     + bb0 + y2.x;
                zbuf[r * 132 + col + 1] = acc2[m][n][rr * 2 + 1] + bb1 + y2.y;
            }
        }
    }
    __syncthreads();

    for (int r = wid; r < 64; r += 8) {
        float v[4]; float s = 0.f;
#pragma unroll
        for (int i = 0; i < 4; ++i) {
            v[i] = zbuf[r * 132 + lane + i * 32];
            s += v[i];
        }
#pragma unroll
        for (int off = 16; off; off >>= 1) s += __shfl_xor_sync(0xffffffffu, s, off);
        float mu = s * (1.0f / 128.0f);
        float vs = 0.f;
#pragma unroll
        for (int i = 0; i < 4; ++i) { float d = v[i] - mu; vs += d * d; }
#pragma unroll
        for (int off = 16; off; off >>= 1) vs += __shfl_xor_sync(0xffffffffu, vs, off);
        float rstd = rsqrtf(vs * (1.0f / 128.0f) + 1e-5f);
#pragma unroll
        for (int i = 0; i < 4; ++i) {
            int ch = lane + i * 32;
            g_bufA[(row0 + r) * CD + ch] =
                (v[i] - mu) * rstd * __ldg(&gamma[ch]) + __ldg(&beta[ch]);
        }
    }

    // ---- fused conv_state for the NEXT depth (skip on last depth) ----
    if (ltau_next) {
        __syncthreads();                   // this block's g_bufA writes now visible
        fused_state(ltau_next, tid, row0);
    }
}

// ---------------- final mean over L ----------------
__global__ __launch_bounds__(512) void mean_kernel(float* __restrict__ out) {
    __shared__ float part[4][128];
    const int b  = blockIdx.x;
    const int c  = threadIdx.x & 127;
    const int lq = threadIdx.x >> 7;
    const float* p = g_bufA + (size_t)b * SEQ * CD + c;
    float s = 0.f;
    for (int l = lq * 128; l < lq * 128 + 128; ++l) s += p[l * CD];
    part[lq][c] = s;
    __syncthreads();
    if (lq == 0)
        out[b * CD + c] = (part[0][c] + part[1][c] + part[2][c] + part[3][c]) * (1.0f / 512.0f);
}

extern "C" void kernel_launch(void* const* d_in, const int* in_sizes, int n_in,
                              void* d_out, int out_size) {
    const float* x     = (const float*)d_in[0];
    const float* Wp    = (const float*)d_in[2];
    const float* bp    = (const float*)d_in[3];
    const float* ltau  = (const float*)d_in[4];
    const float* W_in  = (const float*)d_in[5];
    const float* b_in  = (const float*)d_in[6];
    const float* W_out = (const float*)d_in[7];
    const float* b_out = (const float*)d_in[8];
    const float* gamma = (const float*)d_in[9];
    const float* beta  = (const float*)d_in[10];
    float* out = (float*)d_out;

    cudaFuncSetAttribute(mlp_mma_kernel, cudaFuncAttributeMaxDynamicSharedMemorySize,
                         MMA_SMEM_BYTES);
    cudaFuncSetAttribute(proj_mma_kernel, cudaFuncAttributeMaxDynamicSharedMemorySize,
                         PJ_SMEM);

    stage_w_kernel<<<96, 256>>>(W_in, W_out, Wp);
    proj_mma_kernel<<<NTOK / 64, 256, PJ_SMEM>>>(x, bp, ltau);
    for (int d = 0; d < 3; ++d) {
        conv_emit_kernel<<<NGR * 16, 128>>>(ltau + d * 128);
        const float* lt_next = (d < 2) ? (ltau + (d + 1) * 128) : nullptr;
        mlp_mma_kernel<<<NTOK / 64, 256, MMA_SMEM_BYTES>>>(
            d, b_in + d * 256, b_out + d * 128, gamma + d * 128, beta + d * 128, lt_next);
    }
    mean_kernel<<<NGR, 512>>>(out);
}

// round 17
// speedup vs baseline: 1.0281x; 1.0281x over previous
#include <cuda_runtime.h>
#include <cuda_bf16.h>
#include <cstdint>

#define NTOK 65536
#define CD   128
#define SEQ  512
#define NGR  128

__device__ float g_bufA[(size_t)NTOK * CD];
__device__ float g_bufB[(size_t)NTOK * CD];
__device__ float g_state[NGR * 16 * CD];  // per-(graph, 32-segment, channel) weighted sums
__device__ float g_part[1024 * CD];       // per-(64-row block, channel) output sums (last depth)

// bf16 hi/lo weight images (row-major [n][k])
__device__ __nv_bfloat16 g_WinH[3][256 * 128];
__device__ __nv_bfloat16 g_WinL[3][256 * 128];
__device__ __nv_bfloat16 g_WoutH[3][128 * 128];
__device__ __nv_bfloat16 g_WoutL[3][128 * 128];
__device__ __nv_bfloat16 g_WpH[128 * 64];
__device__ __nv_bfloat16 g_WpL[128 * 64];

__device__ __forceinline__ unsigned int smem_u32(const void* p) {
    unsigned int a;
    asm("{ .reg .u64 t; cvta.to.shared.u64 t, %1; cvt.u32.u64 %0, t; }" : "=r"(a) : "l"(p));
    return a;
}

#define LDSM4(v, addr) \
    asm volatile("ldmatrix.sync.aligned.m8n8.x4.shared.b16 {%0,%1,%2,%3}, [%4];" \
                 : "=r"((v).x), "=r"((v).y), "=r"((v).z), "=r"((v).w) : "r"(addr))

#define MMA_BF16(d, a, b0, b1) \
    asm volatile("mma.sync.aligned.m16n8k16.row.col.f32.bf16.bf16.f32 " \
                 "{%0,%1,%2,%3}, {%4,%5,%6,%7}, {%8,%9}, {%0,%1,%2,%3};" \
                 : "+f"((d)[0]), "+f"((d)[1]), "+f"((d)[2]), "+f"((d)[3]) \
                 : "r"((a).x), "r"((a).y), "r"((a).z), "r"((a).w), "r"(b0), "r"(b1))

// 12 MMAs: 3-term bf16 split for one (m32 x n16) block
#define MMA_BLOCK(c0, c1, c2, c3, ah0, ah1, al0, al1, bh, bl) \
    do { \
        MMA_BF16(c0, ah0, bh.x, bh.y); \
        MMA_BF16(c0, ah0, bl.x, bl.y); \
        MMA_BF16(c0, al0, bh.x, bh.y); \
        MMA_BF16(c1, ah0, bh.z, bh.w); \
        MMA_BF16(c1, ah0, bl.z, bl.w); \
        MMA_BF16(c1, al0, bh.z, bh.w); \
        MMA_BF16(c2, ah1, bh.x, bh.y); \
        MMA_BF16(c2, ah1, bl.x, bl.y); \
        MMA_BF16(c2, al1, bh.x, bh.y); \
        MMA_BF16(c3, ah1, bh.z, bh.w); \
        MMA_BF16(c3, ah1, bl.z, bl.w); \
        MMA_BF16(c3, al1, bh.z, bh.w); \
    } while (0)

// ---------------- weight staging: fp32 -> bf16 hi/lo (96 blocks) ----------------
__global__ __launch_bounds__(256) void stage_w_kernel(const float* __restrict__ W_in,
                                                      const float* __restrict__ W_out,
                                                      const float* __restrict__ Wp) {
    const int d = blockIdx.x >> 5;        // 0..2
    const int gt = (blockIdx.x & 31) * 256 + threadIdx.x;   // 0..8191 within depth
    for (int i = gt; i < 256 * 128; i += 8192) {
        float v = W_in[d * 256 * 128 + i];
        __nv_bfloat16 h = __float2bfloat16(v);
        g_WinH[d][i] = h;
        g_WinL[d][i] = __float2bfloat16(v - __bfloat162float(h));
    }
    for (int i = gt; i < 128 * 128; i += 8192) {
        float v = W_out[d * 128 * 128 + i];
        __nv_bfloat16 h = __float2bfloat16(v);
        g_WoutH[d][i] = h;
        g_WoutL[d][i] = __float2bfloat16(v - __bfloat162float(h));
    }
    if (d == 0) {
        for (int i = gt; i < 128 * 64; i += 8192) {
            float v = Wp[i];
            __nv_bfloat16 h = __float2bfloat16(v);
            g_WpH[i] = h;
            g_WpL[i] = __float2bfloat16(v - __bfloat162float(h));
        }
    }
}

// ---------------- proj via mma.sync: h = x @ Wp^T + bp (R15) ----------------
#define PJ_XH 0
#define PJ_XL 9216
#define PJ_WH 18432
#define PJ_WL 36864
#define PJ_SMEM 55296

__global__ __launch_bounds__(256) void proj_mma_kernel(const float* __restrict__ x,
                                                       const float* __restrict__ bproj) {
    extern __shared__ char smem[];
    const unsigned sb = smem_u32(smem);
    const int tid = threadIdx.x;
    const int wid = tid >> 5, lane = tid & 31;
    const int r0 = (wid >> 2) * 32;
    const int n0 = (wid & 3) * 32;
    const size_t row0 = (size_t)blockIdx.x * 64;

#pragma unroll
    for (int t = 0; t < 8; ++t) {
        int idx = tid + t * 256;          // pair index over 64 x 32
        int r = idx >> 5, kp = idx & 31;
        float2 v2 = *(const float2*)&x[(row0 + r) * 64 + 2 * kp];
        __nv_bfloat16 h0 = __float2bfloat16(v2.x), h1 = __float2bfloat16(v2.y);
        __nv_bfloat16 l0 = __float2bfloat16(v2.x - __bfloat162float(h0));
        __nv_bfloat16 l1 = __float2bfloat16(v2.y - __bfloat162float(h1));
        __nv_bfloat162 hp = __halves2bfloat162(h0, h1);
        __nv_bfloat162 lp = __halves2bfloat162(l0, l1);
        *(unsigned*)(smem + PJ_XH + r * 144 + kp * 4) = *(unsigned*)&hp;
        *(unsigned*)(smem + PJ_XL + r * 144 + kp * 4) = *(unsigned*)&lp;
    }
#pragma unroll
    for (int t = 0; t < 4; ++t) {
        int i = tid + t * 256;            // chunk over 128 x 8
        int r = i >> 3, ck = i & 7;
        *(uint4*)(smem + PJ_WH + r * 144 + ck * 16) = *(const uint4*)((const char*)(g_WpH + r * 64) + ck * 16);
        *(uint4*)(smem + PJ_WL + r * 144 + ck * 16) = *(const uint4*)((const char*)(g_WpL + r * 64) + ck * 16);
    }
    __syncthreads();

    const unsigned browb = (unsigned)((lane & 7) + ((lane & 16) >> 1));
    const unsigned bcolb = (unsigned)(lane & 8);
    float acc[2][4][4];
#pragma unroll
    for (int m = 0; m < 2; ++m)
#pragma unroll
        for (int n = 0; n < 4; ++n)
#pragma unroll
            for (int j = 0; j < 4; ++j) acc[m][n][j] = 0.f;

#pragma unroll
    for (int ks = 0; ks < 4; ++ks) {
        const int k0 = ks * 16;
        unsigned aoff = (unsigned)(r0 + (lane & 15)) * 144u
                      + (unsigned)(k0 + ((lane & 16) >> 1)) * 2u;
        uint4 ah0, ah1, al0, al1;
        LDSM4(ah0, sb + PJ_XH + aoff);
        LDSM4(ah1, sb + PJ_XH + aoff + 16 * 144);
        LDSM4(al0, sb + PJ_XL + aoff);
        LDSM4(al1, sb + PJ_XL + aoff + 16 * 144);
#pragma unroll
        for (int nb = 0; nb < 2; ++nb) {
            unsigned boff = (unsigned)(n0 + nb * 16 + browb) * 144u
                          + (bcolb + (unsigned)k0) * 2u;
            uint4 bh, bl;
            LDSM4(bh, sb + PJ_WH + boff);
            LDSM4(bl, sb + PJ_WL + boff);
            MMA_BLOCK(acc[0][nb * 2], acc[0][nb * 2 + 1], acc[1][nb * 2], acc[1][nb * 2 + 1],
                      ah0, ah1, al0, al1, bh, bl);
        }
    }
    const int rA = (lane >> 2);
    const int cB = (lane & 3) * 2;
#pragma unroll
    for (int m = 0; m < 2; ++m) {
#pragma unroll
        for (int n = 0; n < 4; ++n) {
            const int col = n0 + n * 8 + cB;
            const float bb0 = __ldg(&bproj[col]), bb1 = __ldg(&bproj[col + 1]);
#pragma unroll
            for (int rr = 0; rr < 2; ++rr) {
                const int r = r0 + m * 16 + rA + rr * 8;
                float2 v = make_float2(acc[m][n][rr * 2] + bb0, acc[m][n][rr * 2 + 1] + bb1);
                *(float2*)&g_bufA[(row0 + r) * CD + col] = v;
            }
        }
    }
}

// ---------------- conv phase A: per-32-segment weighted sums (R13/R15) ----------------
__global__ __launch_bounds__(128) void conv_state_kernel(const float* __restrict__ log_tau_d) {
    const int b = blockIdx.x >> 4;
    const int t = blockIdx.x & 15;
    const int c = threadIdx.x;

    float tau = fmaxf(expf(log_tau_d[c]), 0.001f);
    float rho = expf(-1.0f / tau);

    const float* xp = g_bufA + (size_t)b * SEQ * CD + (size_t)(t * 32) * CD + c;
    float P = 0.f;
#pragma unroll 8
    for (int j = 31; j >= 0; --j)      // descending: x[32t+j] gets weight rho^j
        P = fmaf(rho, P, xp[j * CD]);
    g_state[(b * 16 + t) * CD + c] = P;
}

// ---------------- conv phase B: emit using 8 combined states (R13/R15) ----------------
__global__ __launch_bounds__(128) void conv_emit_kernel(const float* __restrict__ log_tau_d) {
    const int b = blockIdx.x >> 4;
    const int q = blockIdx.x & 15;
    const int c = threadIdx.x;

    float tau   = fmaxf(expf(log_tau_d[c]), 0.001f);
    float it    = 1.0f / tau;
    float rho   = expf(-it);
    float rho32 = expf(-32.0f * it);
    float rhoK  = expf(-256.0f * it);
    float den   = 1.0f - rho;
    float S     = (den > 1e-20f) ? (1.0f - rhoK) / den : 256.0f;
    float scale = 1.0f / (S + 1e-8f);

    const float* xp = g_bufA + (size_t)b * SEQ * CD + c;
    float*       yp = g_bufB + (size_t)b * SEQ * CD + c;

    float acc = 0.f;
#pragma unroll
    for (int dd = 0; dd < 8; ++dd) {   // Q_q gets rho32^7, Q_{q-7} gets rho32^0
        int tseg = q - dd;
        float P = (tseg >= 0) ? g_state[(b * 16 + tseg) * CD + c] : 0.f;
        acc = fmaf(rho32, acc, P);
    }

    int l = q * 32 + 31;
#pragma unroll 8
    for (int n = 0; n < 32; ++n, --l) {
        yp[l * CD] = acc * scale;
        float xold = (l >= 256) ? xp[(l - 256) * CD] : 0.f;
        float xtop = xp[l * CD];
        acc = fmaf(rho, acc, fmaf(-rhoK, xtop, xold));
    }
}

// ---------------- mma.sync fused MLP (R15) + fused partial-mean on last depth ----------------
#define SM_YH   0
#define SM_YL   17408
#define SM_W    34816
#define SM_WLO  71680
#define SM_UH   SM_YH
#define SM_UL   SM_YL
#define SM_ZB   SM_YH
#define MMA_SMEM_BYTES 108544

__device__ __forceinline__ void copy_w_pair(char* smem, int tid,
                                            const __nv_bfloat16* __restrict__ h0,
                                            const __nv_bfloat16* __restrict__ l0, int co0,
                                            const __nv_bfloat16* __restrict__ h1,
                                            const __nv_bfloat16* __restrict__ l1, int co1) {
#pragma unroll
    for (int t = 0; t < 8; ++t) {
        int i = tid + t * 256;            // chunk index over 256 rows x 8 chunks
        int r = i >> 3, ck = i & 7;
        const __nv_bfloat16* sH = (r < 128) ? (h0 + r * 128 + co0) : (h1 + (r - 128) * 128 + co1);
        const __nv_bfloat16* sL = (r < 128) ? (l0 + r * 128 + co0) : (l1 + (r - 128) * 128 + co1);
        *(uint4*)(smem + SM_W + r * 144 + ck * 16)   = *(const uint4*)((const char*)sH + ck * 16);
        *(uint4*)(smem + SM_WLO + r * 144 + ck * 16) = *(const uint4*)((const char*)sL + ck * 16);
    }
}

__device__ __forceinline__ void gemm_pair(unsigned sb, unsigned aH, unsigned aL,
                                          int khalf, int r0, int n0, int lane,
                                          float accA[2][4][4], float accG[2][4][4]) {
    const unsigned browb = (unsigned)((lane & 7) + ((lane & 16) >> 1));
    const unsigned bcolb = (unsigned)(lane & 8);
#pragma unroll
    for (int ks = 0; ks < 4; ++ks) {
        const int kA = khalf * 64 + ks * 16;
        unsigned aoff = (unsigned)(r0 + (lane & 15)) * 272u
                      + (unsigned)(kA + ((lane & 16) >> 1)) * 2u;
        uint4 ah0, ah1, al0, al1;
        LDSM4(ah0, sb + aH + aoff);
        LDSM4(ah1, sb + aH + aoff + 16 * 272);
        LDSM4(al0, sb + aL + aoff);
        LDSM4(al1, sb + aL + aoff + 16 * 272);
#pragma unroll
        for (int tgt = 0; tgt < 2; ++tgt) {
            float (*acc)[4][4] = tgt ? (float (*)[4][4])accG : (float (*)[4][4])accA;
#pragma unroll
            for (int nb = 0; nb < 2; ++nb) {
                unsigned boff = (unsigned)(tgt * 128 + n0 + nb * 16 + browb) * 144u
                              + (bcolb + (unsigned)(ks * 16)) * 2u;
                uint4 bh, bl;
                LDSM4(bh, sb + SM_W + boff);
                LDSM4(bl, sb + SM_WLO + boff);
                MMA_BLOCK(acc[0][nb * 2], acc[0][nb * 2 + 1], acc[1][nb * 2], acc[1][nb * 2 + 1],
                          ah0, ah1, al0, al1, bh, bl);
            }
        }
    }
}

__global__ __launch_bounds__(256, 2) void mlp_mma_kernel(int depth,
                                                         const float* __restrict__ b_in,
                                                         const float* __restrict__ b_out,
                                                         const float* __restrict__ gamma,
                                                         const float* __restrict__ beta,
                                                         int is_last) {
    extern __shared__ char smem[];
    const unsigned sb = smem_u32(smem);
    const int tid = threadIdx.x;
    const int wid = tid >> 5, lane = tid & 31;
    const int r0 = (wid >> 2) * 32;
    const int n0 = (wid & 3) * 32;
    const size_t row0 = (size_t)blockIdx.x * 64;

    const __nv_bfloat16* WiH = g_WinH[depth];
    const __nv_bfloat16* WiL = g_WinL[depth];
    const __nv_bfloat16* WoH = g_WoutH[depth];
    const __nv_bfloat16* WoL = g_WoutL[depth];

    copy_w_pair(smem, tid, WiH, WiL, 0, WiH + 128 * 128, WiL + 128 * 128, 0);
#pragma unroll
    for (int t = 0; t < 16; ++t) {
        int idx = tid + t * 256;
        int r = idx >> 6, kp = idx & 63;
        float2 y2 = *(const float2*)&g_bufB[(row0 + r) * CD + 2 * kp];
        __nv_bfloat16 h0 = __float2bfloat16(y2.x), h1 = __float2bfloat16(y2.y);
        __nv_bfloat16 l0 = __float2bfloat16(y2.x - __bfloat162float(h0));
        __nv_bfloat16 l1 = __float2bfloat16(y2.y - __bfloat162float(h1));
        __nv_bfloat162 hp = __halves2bfloat162(h0, h1);
        __nv_bfloat162 lp = __halves2bfloat162(l0, l1);
        *(unsigned*)(smem + SM_YH + r * 272 + kp * 4) = *(unsigned*)&hp;
        *(unsigned*)(smem + SM_YL + r * 272 + kp * 4) = *(unsigned*)&lp;
    }
    __syncthreads();

    float acc_a[2][4][4], acc_g[2][4][4];
#pragma unroll
    for (int m = 0; m < 2; ++m)
#pragma unroll
        for (int n = 0; n < 4; ++n)
#pragma unroll
            for (int j = 0; j < 4; ++j) { acc_a[m][n][j] = 0.f; acc_g[m][n][j] = 0.f; }

    gemm_pair(sb, SM_YH, SM_YL, 0, r0, n0, lane, acc_a, acc_g);
    __syncthreads();
    copy_w_pair(smem, tid, WiH, WiL, 64, WiH + 128 * 128, WiL + 128 * 128, 64);
    __syncthreads();
    gemm_pair(sb, SM_YH, SM_YL, 1, r0, n0, lane, acc_a, acc_g);
    __syncthreads();

    const int rA = (lane >> 2);
    const int cB = (lane & 3) * 2;

#pragma unroll
    for (int m = 0; m < 2; ++m) {
#pragma unroll
        for (int n = 0; n < 4; ++n) {
            const int col = n0 + n * 8 + cB;
            const float ba0 = __ldg(&b_in[col]),       ba1 = __ldg(&b_in[col + 1]);
            const float bg0 = __ldg(&b_in[128 + col]), bg1 = __ldg(&b_in[128 + col + 1]);
#pragma unroll
            for (int rr = 0; rr < 2; ++rr) {
                const int r = r0 + m * 16 + rA + rr * 8;
                float av0 = acc_a[m][n][rr * 2]     + ba0;
                float av1 = acc_a[m][n][rr * 2 + 1] + ba1;
                float gv0 = acc_g[m][n][rr * 2]     + bg0;
                float gv1 = acc_g[m][n][rr * 2 + 1] + bg1;
                float u0 = av0 / (1.0f + expf(-gv0));
                float u1 = av1 / (1.0f + expf(-gv1));
                __nv_bfloat16 h0 = __float2bfloat16(u0), h1 = __float2bfloat16(u1);
                __nv_bfloat16 l0 = __float2bfloat16(u0 - __bfloat162float(h0));
                __nv_bfloat16 l1 = __float2bfloat16(u1 - __bfloat162float(h1));
                __nv_bfloat162 hp = __halves2bfloat162(h0, h1);
                __nv_bfloat162 lp = __halves2bfloat162(l0, l1);
                *(unsigned*)(smem + SM_UH + r * 272 + col * 2) = *(unsigned*)&hp;
                *(unsigned*)(smem + SM_UL + r * 272 + col * 2) = *(unsigned*)&lp;
            }
        }
    }
    copy_w_pair(smem, tid, WoH, WoL, 0, WoH, WoL, 64);
    __syncthreads();

    float acc2[2][4][4];
#pragma unroll
    for (int m = 0; m < 2; ++m)
#pragma unroll
        for (int n = 0; n < 4; ++n)
#pragma unroll
            for (int j = 0; j < 4; ++j) acc2[m][n][j] = 0.f;
    {
        const unsigned browb = (unsigned)((lane & 7) + ((lane & 16) >> 1));
        const unsigned bcolb = (unsigned)(lane & 8);
#pragma unroll
        for (int khalf = 0; khalf < 2; ++khalf) {
#pragma unroll
            for (int ks = 0; ks < 4; ++ks) {
                const int kA = khalf * 64 + ks * 16;
                unsigned aoff = (unsigned)(r0 + (lane & 15)) * 272u
                              + (unsigned)(kA + ((lane & 16) >> 1)) * 2u;
                uint4 ah0, ah1, al0, al1;
                LDSM4(ah0, sb + SM_UH + aoff);
                LDSM4(ah1, sb + SM_UH + aoff + 16 * 272);
                LDSM4(al0, sb + SM_UL + aoff);
                LDSM4(al1, sb + SM_UL + aoff + 16 * 272);
#pragma unroll
                for (int nb = 0; nb < 2; ++nb) {
                    unsigned boff = (unsigned)(khalf * 128 + n0 + nb * 16 + browb) * 144u
                                  + (bcolb + (unsigned)(ks * 16)) * 2u;
                    uint4 bh, bl;
                    LDSM4(bh, sb + SM_W + boff);
                    LDSM4(bl, sb + SM_WLO + boff);
                    MMA_BLOCK(acc2[0][nb * 2], acc2[0][nb * 2 + 1], acc2[1][nb * 2], acc2[1][nb * 2 + 1],
                              ah0, ah1, al0, al1, bh, bl);
                }
            }
        }
    }
    __syncthreads();

    float* zbuf = (float*)(smem + SM_ZB);
#pragma unroll
    for (int m = 0; m < 2; ++m) {
#pragma unroll
        for (int n = 0; n < 4; ++n) {
            const int col = n0 + n * 8 + cB;
            const float bb0 = __ldg(&b_out[col]), bb1 = __ldg(&b_out[col + 1]);
#pragma unroll
            for (int rr = 0; rr < 2; ++rr) {
                const int r = r0 + m * 16 + rA + rr * 8;
                float2 y2 = *(const float2*)&g_bufB[(row0 + r) * CD + col];
                zbuf[r * 132 + col]     = acc2[m][n][rr * 2]     + bb0 + y2.x;
                zbuf[r * 132 + col + 1] = acc2[m][n][rr * 2 + 1] + bb1 + y2.y;
            }
        }
    }
    __syncthreads();

    // ---- LayerNorm per row; normal depths store to g_bufA, last depth accumulates mean partials ----
    float so[4] = {0.f, 0.f, 0.f, 0.f};
    for (int r = wid; r < 64; r += 8) {
        float v[4]; float s = 0.f;
#pragma unroll
        for (int i = 0; i < 4; ++i) {
            v[i] = zbuf[r * 132 + lane + i * 32];
            s += v[i];
        }
#pragma unroll
        for (int off = 16; off; off >>= 1) s += __shfl_xor_sync(0xffffffffu, s, off);
        float mu = s * (1.0f / 128.0f);
        float vs = 0.f;
#pragma unroll
        for (int i = 0; i < 4; ++i) { float d = v[i] - mu; vs += d * d; }
#pragma unroll
        for (int off = 16; off; off >>= 1) vs += __shfl_xor_sync(0xffffffffu, vs, off);
        float rstd = rsqrtf(vs * (1.0f / 128.0f) + 1e-5f);
#pragma unroll
        for (int i = 0; i < 4; ++i) {
            int ch = lane + i * 32;
            float o = (v[i] - mu) * rstd * __ldg(&gamma[ch]) + __ldg(&beta[ch]);
            if (is_last) so[i] += o;
            else g_bufA[(row0 + r) * CD + ch] = o;
        }
    }
    if (is_last) {
        __syncthreads();                 // zbuf reads done; reuse as reduction buffer
        float* red = zbuf;               // 8 warps x 128 channels
#pragma unroll
        for (int i = 0; i < 4; ++i)
            red[wid * 128 + lane + i * 32] = so[i];
        __syncthreads();
        if (tid < 128) {
            float s = 0.f;
#pragma unroll
            for (int k = 0; k < 8; ++k) s += red[k * 128 + tid];
            g_part[blockIdx.x * CD + tid] = s;
        }
    }
}

// ---------------- final mean: reduce 8 block-partials per graph ----------------
__global__ __launch_bounds__(128) void mean_kernel(float* __restrict__ out) {
    const int b = blockIdx.x;
    const int c = threadIdx.x;
    float s = 0.f;
#pragma unroll
    for (int k = 0; k < 8; ++k) s += g_part[(b * 8 + k) * CD + c];
    out[b * CD + c] = s * (1.0f / 512.0f);
}

extern "C" void kernel_launch(void* const* d_in, const int* in_sizes, int n_in,
                              void* d_out, int out_size) {
    const float* x     = (const float*)d_in[0];
    const float* Wp    = (const float*)d_in[2];
    const float* bp    = (const float*)d_in[3];
    const float* ltau  = (const float*)d_in[4];
    const float* W_in  = (const float*)d_in[5];
    const float* b_in  = (const float*)d_in[6];
    const float* W_out = (const float*)d_in[7];
    const float* b_out = (const float*)d_in[8];
    const float* gamma = (const float*)d_in[9];
    const float* beta  = (const float*)d_in[10];
    float* out = (float*)d_out;

    cudaFuncSetAttribute(mlp_mma_kernel, cudaFuncAttributeMaxDynamicSharedMemorySize,
                         MMA_SMEM_BYTES);
    cudaFuncSetAttribute(proj_mma_kernel, cudaFuncAttributeMaxDynamicSharedMemorySize,
                         PJ_SMEM);

    stage_w_kernel<<<96, 256>>>(W_in, W_out, Wp);
    proj_mma_kernel<<<NTOK / 64, 256, PJ_SMEM>>>(x, bp);
    for (int d = 0; d < 3; ++d) {
        conv_state_kernel<<<NGR * 16, 128>>>(ltau + d * 128);
        conv_emit_kernel<<<NGR * 16, 128>>>(ltau + d * 128);
        mlp_mma_kernel<<<NTOK / 64, 256, MMA_SMEM_BYTES>>>(
            d, b_in + d * 256, b_out + d * 128, gamma + d * 128, beta + d * 128,
            (d == 2) ? 1 : 0);
    }
    mean_kernel<<<NGR, 128>>>(out);
}